// round 1
// baseline (speedup 1.0000x reference)
#include <cuda_runtime.h>
#include <cstdint>

// Problem constants
#define BATCH 2
#define SEQ   2048
#define EMBED 1024
#define HEADS 16
#define HS    64            // head size
#define MROWS (BATCH*SEQ)   // 4096
#define N3    (3*EMBED)     // 3072

// Scratch (device globals; no allocation allowed)
__device__ float g_qkv[(size_t)MROWS * N3];     // [B*T, 3C]  (k | q | v)
__device__ float g_att[(size_t)MROWS * EMBED];  // attention output [B*T, C]

// ---------------------------------------------------------------------------
// Register-blocked fp32 GEMM:  C[M,N] = A[M,K] @ B[K,N] + bias[N]
// 128x128 tile, BK=8, 256 threads, 8x8 per thread (split 4+4 to avoid
// smem bank conflicts on LDS.128).
// Requires M%128==0, N%128==0, K%8==0 (true for all our shapes).
// ---------------------------------------------------------------------------
__global__ void __launch_bounds__(256)
gemm_bias_kernel(const float* __restrict__ A, const float* __restrict__ B,
                 const float* __restrict__ bias, float* __restrict__ C,
                 int M, int N, int K)
{
    constexpr int BM = 128, BN = 128, BK = 8;
    __shared__ float As[BK][BM];
    __shared__ float Bs[BK][BN];

    const int tid = threadIdx.x;
    const int row0 = blockIdx.y * BM;
    const int col0 = blockIdx.x * BN;

    const int tx = tid & 15;   // 0..15
    const int ty = tid >> 4;   // 0..15
    const int r0 = ty * 4, r1 = 64 + ty * 4;   // two 4-row groups
    const int c0 = tx * 4, c1 = 64 + tx * 4;   // two 4-col groups

    // A tile load: thread -> (arow, ak) float4
    const int arow = tid >> 1;
    const int ak   = (tid & 1) * 4;
    // B tile load: thread -> (brow, bcol) float4
    const int brow = tid >> 5;
    const int bcol = (tid & 31) * 4;

    const float* Arow = A + (size_t)(row0 + arow) * K;

    float acc[8][8];
    #pragma unroll
    for (int i = 0; i < 8; i++)
        #pragma unroll
        for (int j = 0; j < 8; j++) acc[i][j] = 0.f;

    for (int k0 = 0; k0 < K; k0 += BK) {
        float4 av = *reinterpret_cast<const float4*>(Arow + k0 + ak);
        float4 bv = *reinterpret_cast<const float4*>(B + (size_t)(k0 + brow) * N + col0 + bcol);
        As[ak + 0][arow] = av.x;
        As[ak + 1][arow] = av.y;
        As[ak + 2][arow] = av.z;
        As[ak + 3][arow] = av.w;
        *reinterpret_cast<float4*>(&Bs[brow][bcol]) = bv;
        __syncthreads();

        #pragma unroll
        for (int kk = 0; kk < BK; kk++) {
            float a[8], b[8];
            *reinterpret_cast<float4*>(&a[0]) = *reinterpret_cast<const float4*>(&As[kk][r0]);
            *reinterpret_cast<float4*>(&a[4]) = *reinterpret_cast<const float4*>(&As[kk][r1]);
            *reinterpret_cast<float4*>(&b[0]) = *reinterpret_cast<const float4*>(&Bs[kk][c0]);
            *reinterpret_cast<float4*>(&b[4]) = *reinterpret_cast<const float4*>(&Bs[kk][c1]);
            #pragma unroll
            for (int i = 0; i < 8; i++)
                #pragma unroll
                for (int j = 0; j < 8; j++)
                    acc[i][j] += a[i] * b[j];
        }
        __syncthreads();
    }

    // Epilogue: add bias, store
    #pragma unroll
    for (int i = 0; i < 8; i++) {
        const int r = row0 + (i < 4 ? r0 + i : r1 + (i - 4));
        float* Crow = C + (size_t)r * N;
        #pragma unroll
        for (int g = 0; g < 2; g++) {
            const int cbase = col0 + (g == 0 ? c0 : c1);
            float4 o;
            o.x = acc[i][g * 4 + 0] + bias[cbase + 0];
            o.y = acc[i][g * 4 + 1] + bias[cbase + 1];
            o.z = acc[i][g * 4 + 2] + bias[cbase + 2];
            o.w = acc[i][g * 4 + 3] + bias[cbase + 3];
            *reinterpret_cast<float4*>(Crow + cbase) = o;
        }
    }
}

// ---------------------------------------------------------------------------
// Flash attention (causal), fp32, one query row per thread.
// qkv layout: row (b*T+t) of 3072 floats = [k(1024) | q(1024) | v(1024)]
//   (reference splits qkv as k, q, v — k FIRST).
// Block: 128 threads = 128 consecutive queries of one (b,h).
// K/V streamed through smem in tiles of 16 rows; online softmax in registers.
// ---------------------------------------------------------------------------
#define QB 128
#define KB 16

__global__ void __launch_bounds__(128)
flash_attn_kernel(const float* __restrict__ qkv, float* __restrict__ out)
{
    const int bh = blockIdx.y;            // 0..B*H-1
    const int b  = bh / HEADS;
    const int h  = bh % HEADS;
    const int q0 = blockIdx.x * QB;
    const int tid = threadIdx.x;
    const int tq  = q0 + tid;             // this thread's query index

    __shared__ float Ks[KB][HS];
    __shared__ float Vs[KB][HS];

    const float scale = 0.125f;           // 1/sqrt(64)

    // q row -> registers (q block at offset EMBED within the 3C row)
    float4 q[HS / 4];
    {
        const float* qrow = qkv + ((size_t)(b * SEQ + tq)) * N3 + EMBED + h * HS;
        #pragma unroll
        for (int i = 0; i < HS / 4; i++)
            q[i] = reinterpret_cast<const float4*>(qrow)[i];
    }

    float4 o[HS / 4];
    #pragma unroll
    for (int i = 0; i < HS / 4; i++) o[i] = make_float4(0.f, 0.f, 0.f, 0.f);
    float m = -1e30f, l = 0.f;

    // cooperative-load mapping: 128 threads x 8 floats = 16x64 tile
    const int e  = tid * 8;
    const int jr = e / HS;
    const int dd = e % HS;

    const int kend = q0 + QB;             // keys needed by this block
    for (int j0 = 0; j0 < kend; j0 += KB) {
        __syncthreads();  // previous-iter smem reads done
        {
            const size_t rowbase = ((size_t)(b * SEQ + j0 + jr)) * N3 + h * HS + dd;
            const float* kptr = qkv + rowbase;              // k at offset 0
            const float* vptr = qkv + rowbase + 2 * EMBED;  // v at offset 2C
            *reinterpret_cast<float4*>(&Ks[jr][dd])     = *reinterpret_cast<const float4*>(kptr);
            *reinterpret_cast<float4*>(&Ks[jr][dd + 4]) = *reinterpret_cast<const float4*>(kptr + 4);
            *reinterpret_cast<float4*>(&Vs[jr][dd])     = *reinterpret_cast<const float4*>(vptr);
            *reinterpret_cast<float4*>(&Vs[jr][dd + 4]) = *reinterpret_cast<const float4*>(vptr + 4);
        }
        __syncthreads();

        // scores for this tile
        float s[KB];
        const int jmax = tq - j0;         // key j0+jj valid iff jj <= jmax
        float mt = m;
        #pragma unroll
        for (int jj = 0; jj < KB; jj++) {
            float acc = 0.f;
            #pragma unroll
            for (int i = 0; i < HS / 4; i++) {
                float4 kv = *reinterpret_cast<const float4*>(&Ks[jj][i * 4]);
                acc += q[i].x * kv.x + q[i].y * kv.y + q[i].z * kv.z + q[i].w * kv.w;
            }
            s[jj] = (jj <= jmax) ? acc * scale : -1e30f;
            mt = fmaxf(mt, s[jj]);
        }

        // online softmax rescale (once per tile)
        const float corr = __expf(m - mt);
        m = mt;
        l *= corr;
        #pragma unroll
        for (int i = 0; i < HS / 4; i++) {
            o[i].x *= corr; o[i].y *= corr; o[i].z *= corr; o[i].w *= corr;
        }
        #pragma unroll
        for (int jj = 0; jj < KB; jj++) {
            const float p = __expf(s[jj] - m);
            l += p;
            #pragma unroll
            for (int i = 0; i < HS / 4; i++) {
                float4 vv = *reinterpret_cast<const float4*>(&Vs[jj][i * 4]);
                o[i].x += p * vv.x; o[i].y += p * vv.y;
                o[i].z += p * vv.z; o[i].w += p * vv.w;
            }
        }
    }

    const float inv = 1.f / l;
    float* orow = out + ((size_t)(b * SEQ + tq)) * EMBED + h * HS;
    #pragma unroll
    for (int i = 0; i < HS / 4; i++) {
        float4 v = make_float4(o[i].x * inv, o[i].y * inv, o[i].z * inv, o[i].w * inv);
        reinterpret_cast<float4*>(orow)[i] = v;
    }
}

// ---------------------------------------------------------------------------
extern "C" void kernel_launch(void* const* d_in, const int* in_sizes, int n_in,
                              void* d_out, int out_size)
{
    const float* x       = (const float*)d_in[0];
    const float* W_atten = (const float*)d_in[1];
    const float* b_atten = (const float*)d_in[2];
    const float* W_proj  = (const float*)d_in[3];
    const float* b_proj  = (const float*)d_in[4];
    float* out = (float*)d_out;

    float *qkv = nullptr, *att = nullptr;
    cudaGetSymbolAddress((void**)&qkv, g_qkv);
    cudaGetSymbolAddress((void**)&att, g_att);

    // 1) qkv = x @ W_atten + b_atten   [4096, 3072]
    {
        dim3 grid(N3 / 128, MROWS / 128);
        gemm_bias_kernel<<<grid, 256>>>(x, W_atten, b_atten, qkv, MROWS, N3, EMBED);
    }
    // 2) causal flash attention -> att [4096, 1024]
    {
        dim3 grid(SEQ / QB, BATCH * HEADS);
        flash_attn_kernel<<<grid, 128>>>(qkv, att);
    }
    // 3) out = att @ W_proj + b_proj   [4096, 1024]
    {
        dim3 grid(EMBED / 128, MROWS / 128);
        gemm_bias_kernel<<<grid, 256>>>(att, W_proj, b_proj, out, MROWS, EMBED, EMBED);
    }
}

// round 2
// speedup vs baseline: 1.3259x; 1.3259x over previous
#include <cuda_runtime.h>
#include <cstdint>

// Problem constants
#define BATCH 2
#define SEQ   2048
#define EMBED 1024
#define HEADS 16
#define HS    64            // head size
#define MROWS (BATCH*SEQ)   // 4096
#define N3    (3*EMBED)     // 3072

typedef unsigned long long u64;

// ---------------------------------------------------------------------------
// Packed dual-fp32 helpers (sm_103a f32x2 pipe; rounding identical to scalar)
// ---------------------------------------------------------------------------
__device__ __forceinline__ u64 FFMA2(u64 a, u64 b, u64 c) {
    u64 d;
    asm("fma.rn.f32x2 %0, %1, %2, %3;" : "=l"(d) : "l"(a), "l"(b), "l"(c));
    return d;
}
__device__ __forceinline__ u64 MUL2(u64 a, u64 b) {
    u64 d;
    asm("mul.rn.f32x2 %0, %1, %2;" : "=l"(d) : "l"(a), "l"(b));
    return d;
}
__device__ __forceinline__ u64 pack2(float x, float y) {
    u64 d;
    asm("mov.b64 %0, {%1, %2};" : "=l"(d) : "f"(x), "f"(y));
    return d;
}
__device__ __forceinline__ float2 unpack2(u64 v) {
    float2 f;
    asm("mov.b64 {%0, %1}, %2;" : "=f"(f.x), "=f"(f.y) : "l"(v));
    return f;
}

// Scratch (device globals; no allocation allowed)
__device__ float g_qkv[(size_t)MROWS * N3];     // [B*T, 3C]  (k | q | v)
__device__ float g_att[(size_t)MROWS * EMBED];  // attention output [B*T, C]

// ---------------------------------------------------------------------------
// Register-blocked fp32 GEMM with FFMA2:  C[M,N] = A[M,K] @ B[K,N] + bias[N]
// 128x128 tile, BK=8, 256 threads, 8x8 per thread (packed as 8x4 f32x2).
// ---------------------------------------------------------------------------
__global__ void __launch_bounds__(256)
gemm_bias_kernel(const float* __restrict__ A, const float* __restrict__ B,
                 const float* __restrict__ bias, float* __restrict__ C,
                 int M, int N, int K)
{
    constexpr int BM = 128, BN = 128, BK = 8;
    __shared__ float As[BK][BM];
    __shared__ float Bs[BK][BN];

    const int tid = threadIdx.x;
    const int row0 = blockIdx.y * BM;
    const int col0 = blockIdx.x * BN;

    const int tx = tid & 15;   // 0..15
    const int ty = tid >> 4;   // 0..15
    const int r0 = ty * 4, r1 = 64 + ty * 4;   // two 4-row groups
    const int c0 = tx * 4, c1 = 64 + tx * 4;   // two 4-col groups

    const int arow = tid >> 1;
    const int ak   = (tid & 1) * 4;
    const int brow = tid >> 5;
    const int bcol = (tid & 31) * 4;

    const float* Arow = A + (size_t)(row0 + arow) * K;

    u64 acc2[8][4];
    #pragma unroll
    for (int i = 0; i < 8; i++)
        #pragma unroll
        for (int j = 0; j < 4; j++) acc2[i][j] = 0ull;

    for (int k0 = 0; k0 < K; k0 += BK) {
        float4 av = *reinterpret_cast<const float4*>(Arow + k0 + ak);
        float4 bv = *reinterpret_cast<const float4*>(B + (size_t)(k0 + brow) * N + col0 + bcol);
        As[ak + 0][arow] = av.x;
        As[ak + 1][arow] = av.y;
        As[ak + 2][arow] = av.z;
        As[ak + 3][arow] = av.w;
        *reinterpret_cast<float4*>(&Bs[brow][bcol]) = bv;
        __syncthreads();

        #pragma unroll
        for (int kk = 0; kk < BK; kk++) {
            float a[8];
            *reinterpret_cast<float4*>(&a[0]) = *reinterpret_cast<const float4*>(&As[kk][r0]);
            *reinterpret_cast<float4*>(&a[4]) = *reinterpret_cast<const float4*>(&As[kk][r1]);
            ulonglong2 blo = *reinterpret_cast<const ulonglong2*>(&Bs[kk][c0]);
            ulonglong2 bhi = *reinterpret_cast<const ulonglong2*>(&Bs[kk][c1]);
            u64 bb[4] = {blo.x, blo.y, bhi.x, bhi.y};
            #pragma unroll
            for (int i = 0; i < 8; i++) {
                u64 ai = pack2(a[i], a[i]);
                #pragma unroll
                for (int j = 0; j < 4; j++)
                    acc2[i][j] = FFMA2(ai, bb[j], acc2[i][j]);
            }
        }
        __syncthreads();
    }

    // Epilogue: add bias, store
    #pragma unroll
    for (int i = 0; i < 8; i++) {
        const int r = row0 + (i < 4 ? r0 + i : r1 + (i - 4));
        float* Crow = C + (size_t)r * N;
        #pragma unroll
        for (int g = 0; g < 2; g++) {
            const int cbase = col0 + (g == 0 ? c0 : c1);
            float2 plo = unpack2(acc2[i][g * 2 + 0]);
            float2 phi = unpack2(acc2[i][g * 2 + 1]);
            float4 o;
            o.x = plo.x + bias[cbase + 0];
            o.y = plo.y + bias[cbase + 1];
            o.z = phi.x + bias[cbase + 2];
            o.w = phi.y + bias[cbase + 3];
            *reinterpret_cast<float4*>(Crow + cbase) = o;
        }
    }
}

// ---------------------------------------------------------------------------
// Block-tiled flash attention (causal), fp32 with FFMA2.
// Block: 256 threads = 16x16 grid handling 128 queries of one (b,h).
// Key tiles of 64 streamed through smem. Per thread: 8 rows x 4 cols.
// qkv row layout: [k(1024) | q(1024) | v(1024)]  (k FIRST per reference).
// ---------------------------------------------------------------------------
#define BQ 128
#define BKEY 64

// smem: Qs[64][132] | Ks[64][68] | Vs[64][68] | Ps[128][68]
#define QS_OFF 0
#define KS_OFF (64*132)
#define VS_OFF (KS_OFF + 64*68)
#define PS_OFF (VS_OFF + 64*68)
#define SMEM_FLOATS (PS_OFF + 128*68)
#define SMEM_BYTES (SMEM_FLOATS * 4)

__global__ void __launch_bounds__(256, 2)
flash_attn_kernel(const float* __restrict__ qkv, float* __restrict__ out)
{
    extern __shared__ float sm[];
    float (*Qs)[132] = reinterpret_cast<float(*)[132]>(sm + QS_OFF); // [d][r]
    float (*Ks)[68]  = reinterpret_cast<float(*)[68]>(sm + KS_OFF);  // [d][c]
    float (*Vs)[68]  = reinterpret_cast<float(*)[68]>(sm + VS_OFF);  // [j][d]
    float (*Ps)[68]  = reinterpret_cast<float(*)[68]>(sm + PS_OFF);  // [r][j]

    const int bh = blockIdx.y;
    const int b  = bh >> 4;
    const int h  = bh & 15;
    const int qt = (SEQ / BQ - 1) - blockIdx.x;   // heavy tiles first
    const int q0 = qt * BQ;

    const int tid = threadIdx.x;
    const int tx = tid & 15;
    const int ty = tid >> 4;
    const int r0 = ty * 4, r1 = 64 + ty * 4;
    const int c0 = tx * 4;      // key cols of this thread's score sub-tile
    const int d0 = tx * 4;      // output dims of this thread

    // ---- load Q transposed into smem, pre-scaled by 1/sqrt(hs) ----
    {
        const int rr   = tid & 127;
        const int half = tid >> 7;
        const float* qrow = qkv + (size_t)(b * SEQ + q0 + rr) * N3 + EMBED + h * HS + half * 32;
        #pragma unroll
        for (int i = 0; i < 8; i++) {
            float4 v = reinterpret_cast<const float4*>(qrow)[i];
            const int d = half * 32 + i * 4;
            Qs[d + 0][rr] = v.x * 0.125f;
            Qs[d + 1][rr] = v.y * 0.125f;
            Qs[d + 2][rr] = v.z * 0.125f;
            Qs[d + 3][rr] = v.w * 0.125f;
        }
    }

    u64 o2[8][2];
    float m[8], l[8];
    #pragma unroll
    for (int i = 0; i < 8; i++) {
        o2[i][0] = 0ull; o2[i][1] = 0ull;
        m[i] = -1e30f; l[i] = 0.f;
    }

    const int c    = tid & 63;   // key row this thread loads
    const int quad = tid >> 6;   // which quarter of the dims

    const int kend = q0 + BQ;
    for (int j0 = 0; j0 < kend; j0 += BKEY) {
        __syncthreads();
        // ---- load K (transposed) and V tiles ----
        {
            const size_t base = (size_t)(b * SEQ + j0 + c) * N3 + h * HS;
            #pragma unroll
            for (int s2 = 0; s2 < 4; s2++) {
                const int f = quad * 4 + s2;          // float4 index 0..15
                float4 kv = *reinterpret_cast<const float4*>(qkv + base + f * 4);
                Ks[f * 4 + 0][c] = kv.x;
                Ks[f * 4 + 1][c] = kv.y;
                Ks[f * 4 + 2][c] = kv.z;
                Ks[f * 4 + 3][c] = kv.w;
                float4 vv = *reinterpret_cast<const float4*>(qkv + base + 2 * EMBED + f * 4);
                *reinterpret_cast<float4*>(&Vs[c][f * 4]) = vv;
            }
        }
        __syncthreads();

        // ---- score GEMM: S[128][64] sub-tile per thread (row-pairs x 4 cols) ----
        u64 acc2[4][4];
        #pragma unroll
        for (int ip = 0; ip < 4; ip++)
            #pragma unroll
            for (int j = 0; j < 4; j++) acc2[ip][j] = 0ull;

        #pragma unroll 8
        for (int d = 0; d < 64; d++) {
            ulonglong2 qlo = *reinterpret_cast<const ulonglong2*>(&Qs[d][r0]);
            ulonglong2 qhi = *reinterpret_cast<const ulonglong2*>(&Qs[d][r1]);
            float4 kv = *reinterpret_cast<const float4*>(&Ks[d][c0]);
            u64 a2[4] = {qlo.x, qlo.y, qhi.x, qhi.y};
            u64 b0 = pack2(kv.x, kv.x);
            u64 b1 = pack2(kv.y, kv.y);
            u64 b2 = pack2(kv.z, kv.z);
            u64 b3 = pack2(kv.w, kv.w);
            #pragma unroll
            for (int ip = 0; ip < 4; ip++) {
                acc2[ip][0] = FFMA2(a2[ip], b0, acc2[ip][0]);
                acc2[ip][1] = FFMA2(a2[ip], b1, acc2[ip][1]);
                acc2[ip][2] = FFMA2(a2[ip], b2, acc2[ip][2]);
                acc2[ip][3] = FFMA2(a2[ip], b3, acc2[ip][3]);
            }
        }

        // ---- masking + online softmax (row-wise over 16 tx lanes) ----
        #pragma unroll
        for (int ip = 0; ip < 4; ip++) {
            float2 s0 = unpack2(acc2[ip][0]);
            float2 s1 = unpack2(acc2[ip][1]);
            float2 s2 = unpack2(acc2[ip][2]);
            float2 s3 = unpack2(acc2[ip][3]);
            #pragma unroll
            for (int comp = 0; comp < 2; comp++) {
                const int i   = ip * 2 + comp;
                const int row = (i < 4) ? (r0 + i) : (r1 + (i - 4));
                const int qidx = q0 + row;
                const int kb   = j0 + c0;
                float x0 = comp ? s0.y : s0.x;
                float x1 = comp ? s1.y : s1.x;
                float x2 = comp ? s2.y : s2.x;
                float x3 = comp ? s3.y : s3.x;
                if (kb + 0 > qidx) x0 = -1e30f;
                if (kb + 1 > qidx) x1 = -1e30f;
                if (kb + 2 > qidx) x2 = -1e30f;
                if (kb + 3 > qidx) x3 = -1e30f;
                float tm = fmaxf(fmaxf(x0, x1), fmaxf(x2, x3));
                #pragma unroll
                for (int msk = 1; msk <= 8; msk <<= 1)
                    tm = fmaxf(tm, __shfl_xor_sync(0xffffffffu, tm, msk));
                const float mnew = fmaxf(m[i], tm);
                const float corr = __expf(m[i] - mnew);
                const float p0 = __expf(x0 - mnew);
                const float p1 = __expf(x1 - mnew);
                const float p2 = __expf(x2 - mnew);
                const float p3 = __expf(x3 - mnew);
                float ps = (p0 + p1) + (p2 + p3);
                #pragma unroll
                for (int msk = 1; msk <= 8; msk <<= 1)
                    ps += __shfl_xor_sync(0xffffffffu, ps, msk);
                l[i] = l[i] * corr + ps;
                m[i] = mnew;
                const u64 c2 = pack2(corr, corr);
                o2[i][0] = MUL2(o2[i][0], c2);
                o2[i][1] = MUL2(o2[i][1], c2);
                *reinterpret_cast<float4*>(&Ps[row][c0]) = make_float4(p0, p1, p2, p3);
            }
        }
        __syncthreads();

        // ---- PV GEMM: o[128][64] sub-tile per thread (8 rows x 2 dim-pairs) ----
        #pragma unroll 4
        for (int j4 = 0; j4 < 16; j4++) {
            float4 Pv[8];
            #pragma unroll
            for (int i = 0; i < 8; i++) {
                const int row = (i < 4) ? (r0 + i) : (r1 + (i - 4));
                Pv[i] = *reinterpret_cast<const float4*>(&Ps[row][j4 * 4]);
            }
            #pragma unroll
            for (int t = 0; t < 4; t++) {
                ulonglong2 vv = *reinterpret_cast<const ulonglong2*>(&Vs[j4 * 4 + t][d0]);
                #pragma unroll
                for (int i = 0; i < 8; i++) {
                    const float pv = (t == 0) ? Pv[i].x : (t == 1) ? Pv[i].y
                                   : (t == 2) ? Pv[i].z : Pv[i].w;
                    const u64 pp = pack2(pv, pv);
                    o2[i][0] = FFMA2(pp, vv.x, o2[i][0]);
                    o2[i][1] = FFMA2(pp, vv.y, o2[i][1]);
                }
            }
        }
    }

    // ---- epilogue: normalize by l, store ----
    #pragma unroll
    for (int i = 0; i < 8; i++) {
        const int row = (i < 4) ? (r0 + i) : (r1 + (i - 4));
        const float inv = 1.f / l[i];
        float2 alo = unpack2(o2[i][0]);
        float2 ahi = unpack2(o2[i][1]);
        float4 res = make_float4(alo.x * inv, alo.y * inv, ahi.x * inv, ahi.y * inv);
        float* orow = out + (size_t)(b * SEQ + q0 + row) * EMBED + h * HS + d0;
        *reinterpret_cast<float4*>(orow) = res;
    }
}

// ---------------------------------------------------------------------------
extern "C" void kernel_launch(void* const* d_in, const int* in_sizes, int n_in,
                              void* d_out, int out_size)
{
    const float* x       = (const float*)d_in[0];
    const float* W_atten = (const float*)d_in[1];
    const float* b_atten = (const float*)d_in[2];
    const float* W_proj  = (const float*)d_in[3];
    const float* b_proj  = (const float*)d_in[4];
    float* out = (float*)d_out;

    float *qkv = nullptr, *att = nullptr;
    cudaGetSymbolAddress((void**)&qkv, g_qkv);
    cudaGetSymbolAddress((void**)&att, g_att);

    static bool attr_set = false;
    if (!attr_set) {
        cudaFuncSetAttribute(flash_attn_kernel,
                             cudaFuncAttributeMaxDynamicSharedMemorySize, SMEM_BYTES);
        attr_set = true;
    }

    // 1) qkv = x @ W_atten + b_atten   [4096, 3072]
    {
        dim3 grid(N3 / 128, MROWS / 128);
        gemm_bias_kernel<<<grid, 256>>>(x, W_atten, b_atten, qkv, MROWS, N3, EMBED);
    }
    // 2) causal flash attention -> att [4096, 1024]
    {
        dim3 grid(SEQ / BQ, BATCH * HEADS);
        flash_attn_kernel<<<grid, 256, SMEM_BYTES>>>(qkv, att);
    }
    // 3) out = att @ W_proj + b_proj   [4096, 1024]
    {
        dim3 grid(EMBED / 128, MROWS / 128);
        gemm_bias_kernel<<<grid, 256>>>(att, W_proj, b_proj, out, MROWS, EMBED, EMBED);
    }
}

// round 4
// speedup vs baseline: 1.9341x; 1.4587x over previous
#include <cuda_runtime.h>
#include <cuda_bf16.h>
#include <cstdint>

// Problem constants
#define BATCH 2
#define SEQ   2048
#define EMBED 1024
#define HEADS 16
#define HS    64            // head size
#define MROWS (BATCH*SEQ)   // 4096
#define N3    (3*EMBED)     // 3072

typedef unsigned long long u64;

// ---------------------------------------------------------------------------
// Packed dual-fp32 helpers (used by attention kernel)
// ---------------------------------------------------------------------------
__device__ __forceinline__ u64 FFMA2(u64 a, u64 b, u64 c) {
    u64 d;
    asm("fma.rn.f32x2 %0, %1, %2, %3;" : "=l"(d) : "l"(a), "l"(b), "l"(c));
    return d;
}
__device__ __forceinline__ u64 MUL2(u64 a, u64 b) {
    u64 d;
    asm("mul.rn.f32x2 %0, %1, %2;" : "=l"(d) : "l"(a), "l"(b));
    return d;
}
__device__ __forceinline__ u64 pack2(float x, float y) {
    u64 d;
    asm("mov.b64 %0, {%1, %2};" : "=l"(d) : "f"(x), "f"(y));
    return d;
}
__device__ __forceinline__ float2 unpack2(u64 v) {
    float2 f;
    asm("mov.b64 {%0, %1}, %2;" : "=f"(f.x), "=f"(f.y) : "l"(v));
    return f;
}

__device__ __forceinline__ uint32_t smem_to_u32(const void* smem_ptr) {
    uint32_t addr;
    asm("{ .reg .u64 tmp; cvta.to.shared.u64 tmp, %1; cvt.u32.u64 %0, tmp; }"
        : "=r"(addr) : "l"(smem_ptr));
    return addr;
}

// cp.async (baseline PTX, sm_80+)
__device__ __forceinline__ void cp16(uint32_t sdst, const void* gsrc) {
    asm volatile("cp.async.ca.shared.global [%0], [%1], 16;"
                 :: "r"(sdst), "l"(gsrc) : "memory");
}
#define CP_COMMIT() asm volatile("cp.async.commit_group;" ::: "memory")
#define CP_WAIT1()  asm volatile("cp.async.wait_group 1;" ::: "memory")
#define CP_WAIT0()  asm volatile("cp.async.wait_group 0;" ::: "memory")

// ldmatrix (baseline PTX, sm_75+)
__device__ __forceinline__ void ldsm_x4(uint32_t* r, uint32_t addr) {
    asm volatile("ldmatrix.sync.aligned.m8n8.x4.shared.b16 {%0,%1,%2,%3}, [%4];"
                 : "=r"(r[0]), "=r"(r[1]), "=r"(r[2]), "=r"(r[3]) : "r"(addr));
}
__device__ __forceinline__ void ldsm_x2(uint32_t* r, uint32_t addr) {
    asm volatile("ldmatrix.sync.aligned.m8n8.x2.shared.b16 {%0,%1}, [%2];"
                 : "=r"(r[0]), "=r"(r[1]) : "r"(addr));
}

// mma.sync bf16 (baseline PTX, sm_80+)
__device__ __forceinline__ void mma_bf16(float* d, const uint32_t* a, const uint32_t* b) {
    asm volatile(
        "mma.sync.aligned.m16n8k16.row.col.f32.bf16.bf16.f32 "
        "{%0,%1,%2,%3}, {%4,%5,%6,%7}, {%8,%9}, {%0,%1,%2,%3};"
        : "+f"(d[0]), "+f"(d[1]), "+f"(d[2]), "+f"(d[3])
        : "r"(a[0]), "r"(a[1]), "r"(a[2]), "r"(a[3]), "r"(b[0]), "r"(b[1]));
}

// ---------------------------------------------------------------------------
// Scratch (device globals; no allocation allowed)
// ---------------------------------------------------------------------------
__device__ float g_qkv[(size_t)MROWS * N3];     // [B*T, 3C]  (k | q | v)
__device__ float g_att[(size_t)MROWS * EMBED];  // attention output [B*T, C]
__device__ __nv_bfloat16 g_xhi[(size_t)MROWS * EMBED];
__device__ __nv_bfloat16 g_xlo[(size_t)MROWS * EMBED];
__device__ __nv_bfloat16 g_ahi[(size_t)MROWS * EMBED];
__device__ __nv_bfloat16 g_alo[(size_t)MROWS * EMBED];
__device__ __nv_bfloat16 g_wahi[(size_t)N3 * EMBED];   // W_atten^T [3072][1024]
__device__ __nv_bfloat16 g_walo[(size_t)N3 * EMBED];
__device__ __nv_bfloat16 g_wphi[(size_t)EMBED * EMBED]; // W_proj^T [1024][1024]
__device__ __nv_bfloat16 g_wplo[(size_t)EMBED * EMBED];

// ---------------------------------------------------------------------------
// Elementwise split: x -> bf16 hi + bf16 lo
// ---------------------------------------------------------------------------
__global__ void __launch_bounds__(256)
split_bf16_kernel(const float* __restrict__ x,
                  __nv_bfloat16* __restrict__ hi, __nv_bfloat16* __restrict__ lo,
                  int n4)
{
    int i = blockIdx.x * 256 + threadIdx.x;
    if (i >= n4) return;
    float4 v = reinterpret_cast<const float4*>(x)[i];
    __nv_bfloat16 h0 = __float2bfloat16_rn(v.x);
    __nv_bfloat16 h1 = __float2bfloat16_rn(v.y);
    __nv_bfloat16 h2 = __float2bfloat16_rn(v.z);
    __nv_bfloat16 h3 = __float2bfloat16_rn(v.w);
    __nv_bfloat16 l0 = __float2bfloat16_rn(v.x - __bfloat162float(h0));
    __nv_bfloat16 l1 = __float2bfloat16_rn(v.y - __bfloat162float(h1));
    __nv_bfloat16 l2 = __float2bfloat16_rn(v.z - __bfloat162float(h2));
    __nv_bfloat16 l3 = __float2bfloat16_rn(v.w - __bfloat162float(h3));
    __nv_bfloat162* hp = reinterpret_cast<__nv_bfloat162*>(hi) + i * 2;
    __nv_bfloat162* lp = reinterpret_cast<__nv_bfloat162*>(lo) + i * 2;
    hp[0] = __nv_bfloat162(h0, h1); hp[1] = __nv_bfloat162(h2, h3);
    lp[0] = __nv_bfloat162(l0, l1); lp[1] = __nv_bfloat162(l2, l3);
}

// ---------------------------------------------------------------------------
// Transpose + split: W[K,N] fp32 -> T_hi/T_lo [N,K] bf16
// ---------------------------------------------------------------------------
__global__ void __launch_bounds__(256)
transpose_split_kernel(const float* __restrict__ W,
                       __nv_bfloat16* __restrict__ thi,
                       __nv_bfloat16* __restrict__ tlo,
                       int K, int N)
{
    __shared__ float tile[32][33];
    const int k0 = blockIdx.y * 32;
    const int n0 = blockIdx.x * 32;
    const int tx = threadIdx.x & 31;
    const int ty = threadIdx.x >> 5;   // 0..7
    #pragma unroll
    for (int i = 0; i < 32; i += 8)
        tile[ty + i][tx] = W[(size_t)(k0 + ty + i) * N + n0 + tx];
    __syncthreads();
    #pragma unroll
    for (int i = 0; i < 32; i += 8) {
        float v = tile[tx][ty + i];
        __nv_bfloat16 h = __float2bfloat16_rn(v);
        __nv_bfloat16 l = __float2bfloat16_rn(v - __bfloat162float(h));
        const size_t o = (size_t)(n0 + ty + i) * K + k0 + tx;
        thi[o] = h;
        tlo[o] = l;
    }
}

// ---------------------------------------------------------------------------
// HMMA (mma.sync) 3xBF16 GEMM: C[M,N] = (Ahi+Alo)[M,K] @ (Bhi+Blo)^T[N,K] + bias
// 128x128 CTA tile, 8 warps (64x32 warp tile), K-chunk 32, cp.async double buf.
// ---------------------------------------------------------------------------
#define GBM 128
#define GBN 128
#define GBK 32
#define KPAD 40                    // bf16 elems per smem row (80 B, 16B-mult)
#define MAT_BYTES (128 * KPAD * 2) // 10240 per matrix tile
#define BUF_BYTES (4 * MAT_BYTES)  // Ahi|Alo|Bhi|Blo = 40960
#define MMA_SMEM_BYTES (2 * BUF_BYTES)  // 81920

__global__ void __launch_bounds__(256)
mma_gemm_kernel(const __nv_bfloat16* __restrict__ Ahi,
                const __nv_bfloat16* __restrict__ Alo,
                const __nv_bfloat16* __restrict__ Bhi,   // [N,K]
                const __nv_bfloat16* __restrict__ Blo,   // [N,K]
                const float* __restrict__ bias,
                float* __restrict__ C,
                int M, int N, int K)
{
    extern __shared__ char sm_c[];
    const uint32_t smem_base = smem_to_u32(sm_c);
    const int tid = threadIdx.x;
    const int wid = tid >> 5;
    const int lane = tid & 31;
    const int wm = wid >> 2;      // 0..1  (64-row slab)
    const int wn = wid & 3;       // 0..3  (32-col slab)
    const int row0 = blockIdx.y * GBM;
    const int col0 = blockIdx.x * GBN;

    // cooperative load mapping: 2048 16B-vectors per chunk, 8 per thread
    // v: matrix = v>>9 (0:Ahi 1:Alo 2:Bhi 3:Blo), row=(v&511)>>2, quad=v&3
    const __nv_bfloat16* gbase[4] = {Ahi, Alo, Bhi, Blo};

    float acc[4][4][4];
    #pragma unroll
    for (int mt = 0; mt < 4; mt++)
        #pragma unroll
        for (int nt = 0; nt < 4; nt++)
            #pragma unroll
            for (int j = 0; j < 4; j++) acc[mt][nt][j] = 0.f;

    const int nk = K / GBK;

    // per-lane ldmatrix base offsets (within a buffer)
    const int a_lrow = wm * 64 + (lane & 15);           // + mt*16
    const uint32_t a_lbyte = (uint32_t)a_lrow * (KPAD * 2) + (lane >> 4) * 16;
    const int b_lrow = wn * 32 + (lane & 7);            // + nt*8
    const uint32_t b_lbyte = (uint32_t)b_lrow * (KPAD * 2) + ((lane >> 3) & 1) * 16;

    // issue loads for chunk kc into buffer buf
    auto load_chunk = [&](int kc, int buf) {
        const uint32_t bufoff = (uint32_t)buf * BUF_BYTES;
        #pragma unroll
        for (int i = 0; i < 8; i++) {
            const int v = tid + i * 256;
            const int mat = v >> 9;
            const int r   = (v & 511) >> 2;
            const int q   = v & 3;
            const int grow = (mat < 2 ? row0 : col0) + r;
            const __nv_bfloat16* g = gbase[mat] +
                (size_t)grow * K + kc * GBK + q * 8;
            const uint32_t s = smem_base + bufoff + (uint32_t)mat * MAT_BYTES +
                               (uint32_t)r * (KPAD * 2) + q * 16;
            cp16(s, g);
        }
        CP_COMMIT();
    };

    load_chunk(0, 0);

    for (int kc = 0; kc < nk; kc++) {
        const int buf = kc & 1;
        if (kc + 1 < nk) {
            load_chunk(kc + 1, buf ^ 1);
            CP_WAIT1();
        } else {
            CP_WAIT0();
        }
        __syncthreads();

        const uint32_t boff = smem_base + (uint32_t)buf * BUF_BYTES;
        #pragma unroll
        for (int ks = 0; ks < 2; ks++) {
            const uint32_t kso = ks * 32;   // 16 bf16 = 32 bytes
            uint32_t ah[4][4], al[4][4];
            #pragma unroll
            for (int mt = 0; mt < 4; mt++) {
                const uint32_t off = a_lbyte + (uint32_t)mt * 16 * (KPAD * 2) + kso;
                ldsm_x4(ah[mt], boff + 0 * MAT_BYTES + off);
                ldsm_x4(al[mt], boff + 1 * MAT_BYTES + off);
            }
            uint32_t bh[4][2], bl[4][2];
            #pragma unroll
            for (int nt = 0; nt < 4; nt++) {
                const uint32_t off = b_lbyte + (uint32_t)nt * 8 * (KPAD * 2) + kso;
                ldsm_x2(bh[nt], boff + 2 * MAT_BYTES + off);
                ldsm_x2(bl[nt], boff + 3 * MAT_BYTES + off);
            }
            #pragma unroll
            for (int mt = 0; mt < 4; mt++)
                #pragma unroll
                for (int nt = 0; nt < 4; nt++)
                    mma_bf16(acc[mt][nt], ah[mt], bh[nt]);
            #pragma unroll
            for (int mt = 0; mt < 4; mt++)
                #pragma unroll
                for (int nt = 0; nt < 4; nt++)
                    mma_bf16(acc[mt][nt], ah[mt], bl[nt]);
            #pragma unroll
            for (int mt = 0; mt < 4; mt++)
                #pragma unroll
                for (int nt = 0; nt < 4; nt++)
                    mma_bf16(acc[mt][nt], al[mt], bh[nt]);
        }
        __syncthreads();
    }

    // epilogue: m16n8 accum layout: lane -> row=lane>>2 (+8 for c2/c3),
    // col = (lane&3)*2
    const int erow = row0 + wm * 64 + (lane >> 2);
    const int ecol = col0 + wn * 32 + (lane & 3) * 2;
    #pragma unroll
    for (int mt = 0; mt < 4; mt++) {
        #pragma unroll
        for (int nt = 0; nt < 4; nt++) {
            const int cc = ecol + nt * 8;
            const float2 bv = *reinterpret_cast<const float2*>(bias + cc);
            float* p0 = C + (size_t)(erow + mt * 16) * N + cc;
            float* p1 = C + (size_t)(erow + mt * 16 + 8) * N + cc;
            float2 v0 = make_float2(acc[mt][nt][0] + bv.x, acc[mt][nt][1] + bv.y);
            float2 v1 = make_float2(acc[mt][nt][2] + bv.x, acc[mt][nt][3] + bv.y);
            *reinterpret_cast<float2*>(p0) = v0;
            *reinterpret_cast<float2*>(p1) = v1;
        }
    }
}

// ---------------------------------------------------------------------------
// Block-tiled flash attention (causal), fp32 with FFMA2. (unchanged)
// ---------------------------------------------------------------------------
#define BQ 128
#define BKEY 64

#define QS_OFF 0
#define KS_OFF (64*132)
#define VS_OFF (KS_OFF + 64*68)
#define PS_OFF (VS_OFF + 64*68)
#define SMEM_FLOATS (PS_OFF + 128*68)
#define SMEM_BYTES (SMEM_FLOATS * 4)

__global__ void __launch_bounds__(256, 2)
flash_attn_kernel(const float* __restrict__ qkv, float* __restrict__ out)
{
    extern __shared__ float sm_f[];
    float (*Qs)[132] = reinterpret_cast<float(*)[132]>(sm_f + QS_OFF); // [d][r]
    float (*Ks)[68]  = reinterpret_cast<float(*)[68]>(sm_f + KS_OFF);  // [d][c]
    float (*Vs)[68]  = reinterpret_cast<float(*)[68]>(sm_f + VS_OFF);  // [j][d]
    float (*Ps)[68]  = reinterpret_cast<float(*)[68]>(sm_f + PS_OFF);  // [r][j]

    const int bh = blockIdx.y;
    const int b  = bh >> 4;
    const int h  = bh & 15;
    const int qt = (SEQ / BQ - 1) - blockIdx.x;   // heavy tiles first
    const int q0 = qt * BQ;

    const int tid = threadIdx.x;
    const int tx = tid & 15;
    const int ty = tid >> 4;
    const int r0 = ty * 4, r1 = 64 + ty * 4;
    const int c0 = tx * 4;
    const int d0 = tx * 4;

    {
        const int rr   = tid & 127;
        const int half = tid >> 7;
        const float* qrow = qkv + (size_t)(b * SEQ + q0 + rr) * N3 + EMBED + h * HS + half * 32;
        #pragma unroll
        for (int i = 0; i < 8; i++) {
            float4 v = reinterpret_cast<const float4*>(qrow)[i];
            const int d = half * 32 + i * 4;
            Qs[d + 0][rr] = v.x * 0.125f;
            Qs[d + 1][rr] = v.y * 0.125f;
            Qs[d + 2][rr] = v.z * 0.125f;
            Qs[d + 3][rr] = v.w * 0.125f;
        }
    }

    u64 o2[8][2];
    float m[8], l[8];
    #pragma unroll
    for (int i = 0; i < 8; i++) {
        o2[i][0] = 0ull; o2[i][1] = 0ull;
        m[i] = -1e30f; l[i] = 0.f;
    }

    const int c    = tid & 63;
    const int quad = tid >> 6;

    const int kend = q0 + BQ;
    for (int j0 = 0; j0 < kend; j0 += BKEY) {
        __syncthreads();
        {
            const size_t base = (size_t)(b * SEQ + j0 + c) * N3 + h * HS;
            #pragma unroll
            for (int s2 = 0; s2 < 4; s2++) {
                const int f = quad * 4 + s2;
                float4 kv = *reinterpret_cast<const float4*>(qkv + base + f * 4);
                Ks[f * 4 + 0][c] = kv.x;
                Ks[f * 4 + 1][c] = kv.y;
                Ks[f * 4 + 2][c] = kv.z;
                Ks[f * 4 + 3][c] = kv.w;
                float4 vv = *reinterpret_cast<const float4*>(qkv + base + 2 * EMBED + f * 4);
                *reinterpret_cast<float4*>(&Vs[c][f * 4]) = vv;
            }
        }
        __syncthreads();

        u64 acc2[4][4];
        #pragma unroll
        for (int ip = 0; ip < 4; ip++)
            #pragma unroll
            for (int j = 0; j < 4; j++) acc2[ip][j] = 0ull;

        #pragma unroll 8
        for (int d = 0; d < 64; d++) {
            ulonglong2 qlo = *reinterpret_cast<const ulonglong2*>(&Qs[d][r0]);
            ulonglong2 qhi = *reinterpret_cast<const ulonglong2*>(&Qs[d][r1]);
            float4 kv = *reinterpret_cast<const float4*>(&Ks[d][c0]);
            u64 a2[4] = {qlo.x, qlo.y, qhi.x, qhi.y};
            u64 b0 = pack2(kv.x, kv.x);
            u64 b1 = pack2(kv.y, kv.y);
            u64 b2 = pack2(kv.z, kv.z);
            u64 b3 = pack2(kv.w, kv.w);
            #pragma unroll
            for (int ip = 0; ip < 4; ip++) {
                acc2[ip][0] = FFMA2(a2[ip], b0, acc2[ip][0]);
                acc2[ip][1] = FFMA2(a2[ip], b1, acc2[ip][1]);
                acc2[ip][2] = FFMA2(a2[ip], b2, acc2[ip][2]);
                acc2[ip][3] = FFMA2(a2[ip], b3, acc2[ip][3]);
            }
        }

        #pragma unroll
        for (int ip = 0; ip < 4; ip++) {
            float2 s0 = unpack2(acc2[ip][0]);
            float2 s1 = unpack2(acc2[ip][1]);
            float2 s2 = unpack2(acc2[ip][2]);
            float2 s3 = unpack2(acc2[ip][3]);
            #pragma unroll
            for (int comp = 0; comp < 2; comp++) {
                const int i   = ip * 2 + comp;
                const int row = (i < 4) ? (r0 + i) : (r1 + (i - 4));
                const int qidx = q0 + row;
                const int kb   = j0 + c0;
                float x0 = comp ? s0.y : s0.x;
                float x1 = comp ? s1.y : s1.x;
                float x2 = comp ? s2.y : s2.x;
                float x3 = comp ? s3.y : s3.x;
                if (kb + 0 > qidx) x0 = -1e30f;
                if (kb + 1 > qidx) x1 = -1e30f;
                if (kb + 2 > qidx) x2 = -1e30f;
                if (kb + 3 > qidx) x3 = -1e30f;
                float tm = fmaxf(fmaxf(x0, x1), fmaxf(x2, x3));
                #pragma unroll
                for (int msk = 1; msk <= 8; msk <<= 1)
                    tm = fmaxf(tm, __shfl_xor_sync(0xffffffffu, tm, msk));
                const float mnew = fmaxf(m[i], tm);
                const float corr = __expf(m[i] - mnew);
                const float p0 = __expf(x0 - mnew);
                const float p1 = __expf(x1 - mnew);
                const float p2 = __expf(x2 - mnew);
                const float p3 = __expf(x3 - mnew);
                float ps = (p0 + p1) + (p2 + p3);
                #pragma unroll
                for (int msk = 1; msk <= 8; msk <<= 1)
                    ps += __shfl_xor_sync(0xffffffffu, ps, msk);
                l[i] = l[i] * corr + ps;
                m[i] = mnew;
                const u64 c2 = pack2(corr, corr);
                o2[i][0] = MUL2(o2[i][0], c2);
                o2[i][1] = MUL2(o2[i][1], c2);
                *reinterpret_cast<float4*>(&Ps[row][c0]) = make_float4(p0, p1, p2, p3);
            }
        }
        __syncthreads();

        #pragma unroll 4
        for (int j4 = 0; j4 < 16; j4++) {
            float4 Pv[8];
            #pragma unroll
            for (int i = 0; i < 8; i++) {
                const int row = (i < 4) ? (r0 + i) : (r1 + (i - 4));
                Pv[i] = *reinterpret_cast<const float4*>(&Ps[row][j4 * 4]);
            }
            #pragma unroll
            for (int t = 0; t < 4; t++) {
                ulonglong2 vv = *reinterpret_cast<const ulonglong2*>(&Vs[j4 * 4 + t][d0]);
                #pragma unroll
                for (int i = 0; i < 8; i++) {
                    const float pv = (t == 0) ? Pv[i].x : (t == 1) ? Pv[i].y
                                   : (t == 2) ? Pv[i].z : Pv[i].w;
                    const u64 pp = pack2(pv, pv);
                    o2[i][0] = FFMA2(pp, vv.x, o2[i][0]);
                    o2[i][1] = FFMA2(pp, vv.y, o2[i][1]);
                }
            }
        }
    }

    #pragma unroll
    for (int i = 0; i < 8; i++) {
        const int row = (i < 4) ? (r0 + i) : (r1 + (i - 4));
        const float inv = 1.f / l[i];
        float2 alo = unpack2(o2[i][0]);
        float2 ahi = unpack2(o2[i][1]);
        float4 res = make_float4(alo.x * inv, alo.y * inv, ahi.x * inv, ahi.y * inv);
        float* orow = out + (size_t)(b * SEQ + q0 + row) * EMBED + h * HS + d0;
        *reinterpret_cast<float4*>(orow) = res;
    }
}

// ---------------------------------------------------------------------------
extern "C" void kernel_launch(void* const* d_in, const int* in_sizes, int n_in,
                              void* d_out, int out_size)
{
    const float* x       = (const float*)d_in[0];
    const float* W_atten = (const float*)d_in[1];
    const float* b_atten = (const float*)d_in[2];
    const float* W_proj  = (const float*)d_in[3];
    const float* b_proj  = (const float*)d_in[4];
    float* out = (float*)d_out;

    float *qkv = nullptr, *att = nullptr;
    __nv_bfloat16 *xhi, *xlo, *ahi, *alo, *wahi, *walo, *wphi, *wplo;
    cudaGetSymbolAddress((void**)&qkv, g_qkv);
    cudaGetSymbolAddress((void**)&att, g_att);
    cudaGetSymbolAddress((void**)&xhi, g_xhi);
    cudaGetSymbolAddress((void**)&xlo, g_xlo);
    cudaGetSymbolAddress((void**)&ahi, g_ahi);
    cudaGetSymbolAddress((void**)&alo, g_alo);
    cudaGetSymbolAddress((void**)&wahi, g_wahi);
    cudaGetSymbolAddress((void**)&walo, g_walo);
    cudaGetSymbolAddress((void**)&wphi, g_wphi);
    cudaGetSymbolAddress((void**)&wplo, g_wplo);

    cudaFuncSetAttribute(flash_attn_kernel,
                         cudaFuncAttributeMaxDynamicSharedMemorySize, SMEM_BYTES);
    cudaFuncSetAttribute(mma_gemm_kernel,
                         cudaFuncAttributeMaxDynamicSharedMemorySize, MMA_SMEM_BYTES);

    // 0) prep: split x, transpose+split weights
    {
        const int n4 = MROWS * EMBED / 4;
        split_bf16_kernel<<<(n4 + 255) / 256, 256>>>(x, xhi, xlo, n4);
        dim3 gwa(N3 / 32, EMBED / 32);
        transpose_split_kernel<<<gwa, 256>>>(W_atten, wahi, walo, EMBED, N3);
        dim3 gwp(EMBED / 32, EMBED / 32);
        transpose_split_kernel<<<gwp, 256>>>(W_proj, wphi, wplo, EMBED, EMBED);
    }
    // 1) qkv = x @ W_atten + b_atten   [4096, 3072]  (HMMA 3xbf16)
    {
        dim3 grid(N3 / GBN, MROWS / GBM);
        mma_gemm_kernel<<<grid, 256, MMA_SMEM_BYTES>>>(
            xhi, xlo, wahi, walo, b_atten, qkv, MROWS, N3, EMBED);
    }
    // 2) causal flash attention -> att [4096, 1024]
    {
        dim3 grid(SEQ / BQ, BATCH * HEADS);
        flash_attn_kernel<<<grid, 256, SMEM_BYTES>>>(qkv, att);
    }
    // 3) split att, then out = att @ W_proj + b_proj  (HMMA 3xbf16)
    {
        const int n4 = MROWS * EMBED / 4;
        split_bf16_kernel<<<(n4 + 255) / 256, 256>>>(att, ahi, alo, n4);
        dim3 grid(EMBED / GBN, MROWS / GBM);
        mma_gemm_kernel<<<grid, 256, MMA_SMEM_BYTES>>>(
            ahi, alo, wphi, wplo, b_proj, out, MROWS, EMBED, EMBED);
    }
}

// round 5
// speedup vs baseline: 3.1702x; 1.6391x over previous
#include <cuda_runtime.h>
#include <cuda_bf16.h>
#include <cstdint>

// Problem constants
#define BATCH 2
#define SEQ   2048
#define EMBED 1024
#define HEADS 16
#define HS    64            // head size
#define MROWS (BATCH*SEQ)   // 4096
#define N3    (3*EMBED)     // 3072

__device__ __forceinline__ uint32_t smem_to_u32(const void* smem_ptr) {
    uint32_t addr;
    asm("{ .reg .u64 tmp; cvta.to.shared.u64 tmp, %1; cvt.u32.u64 %0, tmp; }"
        : "=r"(addr) : "l"(smem_ptr));
    return addr;
}

// cp.async (baseline PTX, sm_80+)
__device__ __forceinline__ void cp16(uint32_t sdst, const void* gsrc) {
    asm volatile("cp.async.ca.shared.global [%0], [%1], 16;"
                 :: "r"(sdst), "l"(gsrc) : "memory");
}
#define CP_COMMIT() asm volatile("cp.async.commit_group;" ::: "memory")
#define CP_WAIT1()  asm volatile("cp.async.wait_group 1;" ::: "memory")
#define CP_WAIT0()  asm volatile("cp.async.wait_group 0;" ::: "memory")

// ldmatrix (baseline PTX, sm_75+)
__device__ __forceinline__ void ldsm_x4(uint32_t* r, uint32_t addr) {
    asm volatile("ldmatrix.sync.aligned.m8n8.x4.shared.b16 {%0,%1,%2,%3}, [%4];"
                 : "=r"(r[0]), "=r"(r[1]), "=r"(r[2]), "=r"(r[3]) : "r"(addr));
}
__device__ __forceinline__ void ldsm_x2(uint32_t* r, uint32_t addr) {
    asm volatile("ldmatrix.sync.aligned.m8n8.x2.shared.b16 {%0,%1}, [%2];"
                 : "=r"(r[0]), "=r"(r[1]) : "r"(addr));
}
__device__ __forceinline__ void ldsm_x2t(uint32_t* r, uint32_t addr) {
    asm volatile("ldmatrix.sync.aligned.m8n8.x2.trans.shared.b16 {%0,%1}, [%2];"
                 : "=r"(r[0]), "=r"(r[1]) : "r"(addr));
}

// mma.sync bf16 (baseline PTX, sm_80+)
__device__ __forceinline__ void mma_bf16(float* d, const uint32_t* a, const uint32_t* b) {
    asm volatile(
        "mma.sync.aligned.m16n8k16.row.col.f32.bf16.bf16.f32 "
        "{%0,%1,%2,%3}, {%4,%5,%6,%7}, {%8,%9}, {%0,%1,%2,%3};"
        : "+f"(d[0]), "+f"(d[1]), "+f"(d[2]), "+f"(d[3])
        : "r"(a[0]), "r"(a[1]), "r"(a[2]), "r"(a[3]), "r"(b[0]), "r"(b[1]));
}

// FMA-pipe exp2 (no MUFU): x in [-1e30, 0], clamped to [-120, 0]
__device__ __forceinline__ float exp2_fast(float x) {
    x = fmaxf(x, -120.f);
    float c = x + 12582912.f;                    // round to nearest int
    int   n = __float_as_int(c) - 0x4B400000;    // = rint(x)
    float f = x - (c - 12582912.f);              // f in [-0.5, 0.5]
    float p =          0.00133335581f;
    p = fmaf(p, f, 0.00961812911f);
    p = fmaf(p, f, 0.0555041087f);
    p = fmaf(p, f, 0.240226507f);
    p = fmaf(p, f, 0.693147180f);
    p = fmaf(p, f, 1.0f);
    return __int_as_float(__float_as_int(p) + (n << 23));
}

__device__ __forceinline__ uint32_t bf16pack(__nv_bfloat16 x, __nv_bfloat16 y) {
    return (uint32_t)__bfloat16_as_ushort(x) |
           ((uint32_t)__bfloat16_as_ushort(y) << 16);
}
// split-pack: hi/lo bf16 pair registers from two floats
__device__ __forceinline__ void split_pack(float x, float y, uint32_t& hi, uint32_t& lo) {
    __nv_bfloat16 hx = __float2bfloat16_rn(x);
    __nv_bfloat16 hy = __float2bfloat16_rn(y);
    __nv_bfloat16 lx = __float2bfloat16_rn(x - __bfloat162float(hx));
    __nv_bfloat16 ly = __float2bfloat16_rn(y - __bfloat162float(hy));
    hi = bf16pack(hx, hy);
    lo = bf16pack(lx, ly);
}
__device__ __forceinline__ void store_split(__nv_bfloat16* ph, __nv_bfloat16* pl,
                                            float x, float y) {
    __nv_bfloat16 hx = __float2bfloat16_rn(x);
    __nv_bfloat16 hy = __float2bfloat16_rn(y);
    __nv_bfloat162 hv; hv.x = hx; hv.y = hy;
    __nv_bfloat162 lv;
    lv.x = __float2bfloat16_rn(x - __bfloat162float(hx));
    lv.y = __float2bfloat16_rn(y - __bfloat162float(hy));
    *reinterpret_cast<__nv_bfloat162*>(ph) = hv;
    *reinterpret_cast<__nv_bfloat162*>(pl) = lv;
}

// ---------------------------------------------------------------------------
// Scratch (device globals; no allocation allowed)
// ---------------------------------------------------------------------------
__device__ __nv_bfloat16 g_qkvh[(size_t)MROWS * N3];
__device__ __nv_bfloat16 g_qkvl[(size_t)MROWS * N3];
__device__ __nv_bfloat16 g_xhi[(size_t)MROWS * EMBED];
__device__ __nv_bfloat16 g_xlo[(size_t)MROWS * EMBED];
__device__ __nv_bfloat16 g_ahi[(size_t)MROWS * EMBED];
__device__ __nv_bfloat16 g_alo[(size_t)MROWS * EMBED];
__device__ __nv_bfloat16 g_wahi[(size_t)N3 * EMBED];
__device__ __nv_bfloat16 g_walo[(size_t)N3 * EMBED];
__device__ __nv_bfloat16 g_wphi[(size_t)EMBED * EMBED];
__device__ __nv_bfloat16 g_wplo[(size_t)EMBED * EMBED];

// ---------------------------------------------------------------------------
// Elementwise split: x -> bf16 hi + bf16 lo
// ---------------------------------------------------------------------------
__global__ void __launch_bounds__(256)
split_bf16_kernel(const float* __restrict__ x,
                  __nv_bfloat16* __restrict__ hi, __nv_bfloat16* __restrict__ lo,
                  int n4)
{
    int i = blockIdx.x * 256 + threadIdx.x;
    if (i >= n4) return;
    float4 v = reinterpret_cast<const float4*>(x)[i];
    store_split(hi + i * 4,     lo + i * 4,     v.x, v.y);
    store_split(hi + i * 4 + 2, lo + i * 4 + 2, v.z, v.w);
}

// ---------------------------------------------------------------------------
// Transpose + split: W[K,N] fp32 -> T_hi/T_lo [N,K] bf16
// ---------------------------------------------------------------------------
__global__ void __launch_bounds__(256)
transpose_split_kernel(const float* __restrict__ W,
                       __nv_bfloat16* __restrict__ thi,
                       __nv_bfloat16* __restrict__ tlo,
                       int K, int N)
{
    __shared__ float tile[32][33];
    const int k0 = blockIdx.y * 32;
    const int n0 = blockIdx.x * 32;
    const int tx = threadIdx.x & 31;
    const int ty = threadIdx.x >> 5;
    #pragma unroll
    for (int i = 0; i < 32; i += 8)
        tile[ty + i][tx] = W[(size_t)(k0 + ty + i) * N + n0 + tx];
    __syncthreads();
    #pragma unroll
    for (int i = 0; i < 32; i += 8) {
        float v = tile[tx][ty + i];
        __nv_bfloat16 h = __float2bfloat16_rn(v);
        __nv_bfloat16 l = __float2bfloat16_rn(v - __bfloat162float(h));
        const size_t o = (size_t)(n0 + ty + i) * K + k0 + tx;
        thi[o] = h;
        tlo[o] = l;
    }
}

// ---------------------------------------------------------------------------
// HMMA 3xBF16 GEMM: C = (Ahi+Alo)[M,K] @ (Bhi+Blo)^T[N,K] + bias
// Output either fp32 (Cf) or split bf16 (Ch/Cl).
// ---------------------------------------------------------------------------
#define GBM 128
#define GBN 128
#define GBK 32
#define KPAD 40
#define MAT_BYTES (128 * KPAD * 2)
#define BUF_BYTES (4 * MAT_BYTES)
#define MMA_SMEM_BYTES (2 * BUF_BYTES)

__global__ void __launch_bounds__(256)
mma_gemm_kernel(const __nv_bfloat16* __restrict__ Ahi,
                const __nv_bfloat16* __restrict__ Alo,
                const __nv_bfloat16* __restrict__ Bhi,
                const __nv_bfloat16* __restrict__ Blo,
                const float* __restrict__ bias,
                float* __restrict__ Cf,
                __nv_bfloat16* __restrict__ Ch,
                __nv_bfloat16* __restrict__ Cl,
                int M, int N, int K)
{
    extern __shared__ char sm_c[];
    const uint32_t smem_base = smem_to_u32(sm_c);
    const int tid = threadIdx.x;
    const int wid = tid >> 5;
    const int lane = tid & 31;
    const int wm = wid >> 2;
    const int wn = wid & 3;
    const int row0 = blockIdx.y * GBM;
    const int col0 = blockIdx.x * GBN;

    const __nv_bfloat16* gbase[4] = {Ahi, Alo, Bhi, Blo};

    float acc[4][4][4];
    #pragma unroll
    for (int mt = 0; mt < 4; mt++)
        #pragma unroll
        for (int nt = 0; nt < 4; nt++)
            #pragma unroll
            for (int j = 0; j < 4; j++) acc[mt][nt][j] = 0.f;

    const int nk = K / GBK;

    const int a_lrow = wm * 64 + (lane & 15);
    const uint32_t a_lbyte = (uint32_t)a_lrow * (KPAD * 2) + (lane >> 4) * 16;
    const int b_lrow = wn * 32 + (lane & 7);
    const uint32_t b_lbyte = (uint32_t)b_lrow * (KPAD * 2) + ((lane >> 3) & 1) * 16;

    auto load_chunk = [&](int kc, int buf) {
        const uint32_t bufoff = (uint32_t)buf * BUF_BYTES;
        #pragma unroll
        for (int i = 0; i < 8; i++) {
            const int v = tid + i * 256;
            const int mat = v >> 9;
            const int r   = (v & 511) >> 2;
            const int q   = v & 3;
            const int grow = (mat < 2 ? row0 : col0) + r;
            const __nv_bfloat16* g = gbase[mat] +
                (size_t)grow * K + kc * GBK + q * 8;
            const uint32_t s = smem_base + bufoff + (uint32_t)mat * MAT_BYTES +
                               (uint32_t)r * (KPAD * 2) + q * 16;
            cp16(s, g);
        }
        CP_COMMIT();
    };

    load_chunk(0, 0);

    for (int kc = 0; kc < nk; kc++) {
        const int buf = kc & 1;
        if (kc + 1 < nk) {
            load_chunk(kc + 1, buf ^ 1);
            CP_WAIT1();
        } else {
            CP_WAIT0();
        }
        __syncthreads();

        const uint32_t boff = smem_base + (uint32_t)buf * BUF_BYTES;
        #pragma unroll
        for (int ks = 0; ks < 2; ks++) {
            const uint32_t kso = ks * 32;
            uint32_t ah[4][4], al[4][4];
            #pragma unroll
            for (int mt = 0; mt < 4; mt++) {
                const uint32_t off = a_lbyte + (uint32_t)mt * 16 * (KPAD * 2) + kso;
                ldsm_x4(ah[mt], boff + 0 * MAT_BYTES + off);
                ldsm_x4(al[mt], boff + 1 * MAT_BYTES + off);
            }
            uint32_t bh[4][2], bl[4][2];
            #pragma unroll
            for (int nt = 0; nt < 4; nt++) {
                const uint32_t off = b_lbyte + (uint32_t)nt * 8 * (KPAD * 2) + kso;
                ldsm_x2(bh[nt], boff + 2 * MAT_BYTES + off);
                ldsm_x2(bl[nt], boff + 3 * MAT_BYTES + off);
            }
            #pragma unroll
            for (int mt = 0; mt < 4; mt++)
                #pragma unroll
                for (int nt = 0; nt < 4; nt++)
                    mma_bf16(acc[mt][nt], ah[mt], bh[nt]);
            #pragma unroll
            for (int mt = 0; mt < 4; mt++)
                #pragma unroll
                for (int nt = 0; nt < 4; nt++)
                    mma_bf16(acc[mt][nt], ah[mt], bl[nt]);
            #pragma unroll
            for (int mt = 0; mt < 4; mt++)
                #pragma unroll
                for (int nt = 0; nt < 4; nt++)
                    mma_bf16(acc[mt][nt], al[mt], bh[nt]);
        }
        __syncthreads();
    }

    const int erow = row0 + wm * 64 + (lane >> 2);
    const int ecol = col0 + wn * 32 + (lane & 3) * 2;
    #pragma unroll
    for (int mt = 0; mt < 4; mt++) {
        #pragma unroll
        for (int nt = 0; nt < 4; nt++) {
            const int cc = ecol + nt * 8;
            const float2 bv = *reinterpret_cast<const float2*>(bias + cc);
            const size_t o0 = (size_t)(erow + mt * 16) * N + cc;
            const size_t o1 = (size_t)(erow + mt * 16 + 8) * N + cc;
            const float v00 = acc[mt][nt][0] + bv.x, v01 = acc[mt][nt][1] + bv.y;
            const float v10 = acc[mt][nt][2] + bv.x, v11 = acc[mt][nt][3] + bv.y;
            if (Cf) {
                *reinterpret_cast<float2*>(Cf + o0) = make_float2(v00, v01);
                *reinterpret_cast<float2*>(Cf + o1) = make_float2(v10, v11);
            } else {
                store_split(Ch + o0, Cl + o0, v00, v01);
                store_split(Ch + o1, Cl + o1, v10, v11);
            }
        }
    }
}

// ---------------------------------------------------------------------------
// HMMA flash attention (causal), 3xBF16 split, FMA-pipe exp.
// Block: 256 threads (8 warps). 128 queries per block, key tiles of 64.
// Warp w owns rows [w*16, w*16+16). qkv hi/lo rows: [k | q | v] (k first).
// ---------------------------------------------------------------------------
#define BQ 128
#define BKEY 64
#define ATS 72                       // padded bf16 row stride
#define ATSB (ATS*2)                 // 144 bytes
#define QH_OFF 0
#define QL_OFF (QH_OFF + 128*ATSB)
#define KH_OFF (QL_OFF + 128*ATSB)
#define KL_OFF (KH_OFF + 64*ATSB)
#define VH_OFF (KL_OFF + 64*ATSB)
#define VL_OFF (VH_OFF + 64*ATSB)
#define ATT_SMEM (VL_OFF + 64*ATSB)  // 73728

__global__ void __launch_bounds__(256)
flash_attn_hmma(const __nv_bfloat16* __restrict__ qkvh,
                const __nv_bfloat16* __restrict__ qkvl,
                __nv_bfloat16* __restrict__ ahi,
                __nv_bfloat16* __restrict__ alo)
{
    extern __shared__ char sm_c[];
    const uint32_t sb = smem_to_u32(sm_c);
    const int tid = threadIdx.x;
    const int w = tid >> 5;
    const int lane = tid & 31;
    const int bh = blockIdx.y;
    const int b = bh >> 4;
    const int h = bh & 15;
    const int q0 = ((SEQ / BQ - 1) - (int)blockIdx.x) * BQ;

    // ---- Q tile load (hi/lo), once ----
    {
        #pragma unroll
        for (int i = 0; i < 8; i++) {
            const int v = tid + i * 256;
            const int sel = v >> 10;               // 0 hi, 1 lo
            const int r = (v & 1023) >> 3;
            const int ch = v & 7;
            const __nv_bfloat16* src = (sel ? qkvl : qkvh)
                + (size_t)(b * SEQ + q0 + r) * N3 + EMBED + h * HS + ch * 8;
            cp16(sb + (sel ? QL_OFF : QH_OFF) + r * ATSB + ch * 16, src);
        }
        CP_COMMIT();
    }

    float oa[8][4];
    #pragma unroll
    for (int nt = 0; nt < 8; nt++)
        #pragma unroll
        for (int j = 0; j < 4; j++) oa[nt][j] = 0.f;
    float m_a = -1e30f, m_b = -1e30f, l_a = 0.f, l_b = 0.f;

    const float tscale = 0.18033688011f;      // 0.125 * log2(e)
    const int qrow_a = q0 + w * 16 + (lane >> 2);   // row for c0/c1
    const int kend = q0 + BQ;

    // ldmatrix per-lane base offsets
    const uint32_t qa_base = sb + QH_OFF +
        (uint32_t)(w * 16 + (lane & 15)) * ATSB + (lane >> 4) * 16;
    const uint32_t ka_base = sb + KH_OFF +
        (uint32_t)(lane & 7) * ATSB + ((lane >> 3) & 1) * 16;

    for (int j0 = 0; j0 < kend; j0 += BKEY) {
        __syncthreads();
        // ---- K/V tile load (hi/lo) ----
        #pragma unroll
        for (int i = 0; i < 8; i++) {
            const int v = tid + i * 256;
            const int mat = v >> 9;               // 0 Kh,1 Kl,2 Vh,3 Vl
            const int key = (v & 511) >> 3;
            const int ch = v & 7;
            const __nv_bfloat16* base = (mat & 1) ? qkvl : qkvh;
            const int voff = (mat >= 2) ? 2 * EMBED : 0;
            const __nv_bfloat16* src = base +
                (size_t)(b * SEQ + j0 + key) * N3 + voff + h * HS + ch * 8;
            const uint32_t doff = (mat == 0) ? KH_OFF : (mat == 1) ? KL_OFF
                                : (mat == 2) ? VH_OFF : VL_OFF;
            cp16(sb + doff + key * ATSB + ch * 16, src);
        }
        CP_COMMIT();
        CP_WAIT0();
        __syncthreads();

        // ---- S = Q K^T (3-term bf16 split), warp tile 16x64 ----
        float sa[8][4];
        #pragma unroll
        for (int nt = 0; nt < 8; nt++)
            #pragma unroll
            for (int j = 0; j < 4; j++) sa[nt][j] = 0.f;

        #pragma unroll
        for (int ks = 0; ks < 4; ks++) {
            uint32_t ah[4], al[4];
            ldsm_x4(ah, qa_base + ks * 32);
            ldsm_x4(al, qa_base + (QL_OFF - QH_OFF) + ks * 32);
            #pragma unroll
            for (int nt = 0; nt < 8; nt++) {
                uint32_t bh2[2], bl2[2];
                const uint32_t ka = ka_base + (uint32_t)nt * 8 * ATSB + ks * 32;
                ldsm_x2(bh2, ka);
                ldsm_x2(bl2, ka + (KL_OFF - KH_OFF));
                mma_bf16(sa[nt], ah, bh2);
                mma_bf16(sa[nt], ah, bl2);
                mma_bf16(sa[nt], al, bh2);
            }
        }

        // ---- scale + causal mask ----
        if (j0 + BKEY > q0) {
            #pragma unroll
            for (int nt = 0; nt < 8; nt++) {
                const int kb = j0 + nt * 8 + (lane & 3) * 2;
                #pragma unroll
                for (int j = 0; j < 4; j++) {
                    const int key = kb + (j & 1);
                    const int qr = (j < 2) ? qrow_a : qrow_a + 8;
                    sa[nt][j] = (key > qr) ? -1e30f : sa[nt][j] * tscale;
                }
            }
        } else {
            #pragma unroll
            for (int nt = 0; nt < 8; nt++)
                #pragma unroll
                for (int j = 0; j < 4; j++) sa[nt][j] *= tscale;
        }

        // ---- online softmax (rows a: c0/c1, rows b: c2/c3) ----
        float mxa = -1e30f, mxb = -1e30f;
        #pragma unroll
        for (int nt = 0; nt < 8; nt++) {
            mxa = fmaxf(mxa, fmaxf(sa[nt][0], sa[nt][1]));
            mxb = fmaxf(mxb, fmaxf(sa[nt][2], sa[nt][3]));
        }
        mxa = fmaxf(mxa, __shfl_xor_sync(0xffffffffu, mxa, 1));
        mxa = fmaxf(mxa, __shfl_xor_sync(0xffffffffu, mxa, 2));
        mxb = fmaxf(mxb, __shfl_xor_sync(0xffffffffu, mxb, 1));
        mxb = fmaxf(mxb, __shfl_xor_sync(0xffffffffu, mxb, 2));

        const float mna = fmaxf(m_a, mxa);
        const float mnb = fmaxf(m_b, mxb);
        const float ca = exp2_fast(m_a - mna);
        const float cb = exp2_fast(m_b - mnb);
        m_a = mna; m_b = mnb;

        float suma = 0.f, sumb = 0.f;
        #pragma unroll
        for (int nt = 0; nt < 8; nt++) {
            sa[nt][0] = exp2_fast(sa[nt][0] - mna);
            sa[nt][1] = exp2_fast(sa[nt][1] - mna);
            sa[nt][2] = exp2_fast(sa[nt][2] - mnb);
            sa[nt][3] = exp2_fast(sa[nt][3] - mnb);
            suma += sa[nt][0] + sa[nt][1];
            sumb += sa[nt][2] + sa[nt][3];
        }
        suma += __shfl_xor_sync(0xffffffffu, suma, 1);
        suma += __shfl_xor_sync(0xffffffffu, suma, 2);
        sumb += __shfl_xor_sync(0xffffffffu, sumb, 1);
        sumb += __shfl_xor_sync(0xffffffffu, sumb, 2);
        l_a = l_a * ca + suma;
        l_b = l_b * cb + sumb;

        #pragma unroll
        for (int nt = 0; nt < 8; nt++) {
            oa[nt][0] *= ca; oa[nt][1] *= ca;
            oa[nt][2] *= cb; oa[nt][3] *= cb;
        }

        // ---- O += P V (3-term bf16 split) ----
        #pragma unroll
        for (int ks = 0; ks < 4; ks++) {
            const int t0 = 2 * ks, t1 = 2 * ks + 1;
            uint32_t ph[4], pl[4];
            split_pack(sa[t0][0], sa[t0][1], ph[0], pl[0]);
            split_pack(sa[t0][2], sa[t0][3], ph[1], pl[1]);
            split_pack(sa[t1][0], sa[t1][1], ph[2], pl[2]);
            split_pack(sa[t1][2], sa[t1][3], ph[3], pl[3]);
            const uint32_t va = sb + VH_OFF +
                (uint32_t)(ks * 16 + (lane & 7) + ((lane >> 3) & 1) * 8) * ATSB;
            #pragma unroll
            for (int ntd = 0; ntd < 8; ntd++) {
                uint32_t vh2[2], vl2[2];
                ldsm_x2t(vh2, va + ntd * 16);
                ldsm_x2t(vl2, va + (VL_OFF - VH_OFF) + ntd * 16);
                mma_bf16(oa[ntd], ph, vh2);
                mma_bf16(oa[ntd], ph, vl2);
                mma_bf16(oa[ntd], pl, vh2);
            }
        }
    }

    // ---- epilogue: normalize, split-store bf16 hi/lo ----
    const float ia = 1.f / l_a;
    const float ib = 1.f / l_b;
    const size_t rowa = (size_t)(b * SEQ + qrow_a) * EMBED + h * HS;
    const size_t rowb = rowa + 8 * EMBED;
    #pragma unroll
    for (int nt = 0; nt < 8; nt++) {
        const int d = nt * 8 + (lane & 3) * 2;
        store_split(ahi + rowa + d, alo + rowa + d, oa[nt][0] * ia, oa[nt][1] * ia);
        store_split(ahi + rowb + d, alo + rowb + d, oa[nt][2] * ib, oa[nt][3] * ib);
    }
}

// ---------------------------------------------------------------------------
extern "C" void kernel_launch(void* const* d_in, const int* in_sizes, int n_in,
                              void* d_out, int out_size)
{
    const float* x       = (const float*)d_in[0];
    const float* W_atten = (const float*)d_in[1];
    const float* b_atten = (const float*)d_in[2];
    const float* W_proj  = (const float*)d_in[3];
    const float* b_proj  = (const float*)d_in[4];
    float* out = (float*)d_out;

    __nv_bfloat16 *qkvh, *qkvl, *xhi, *xlo, *ahi, *alo, *wahi, *walo, *wphi, *wplo;
    cudaGetSymbolAddress((void**)&qkvh, g_qkvh);
    cudaGetSymbolAddress((void**)&qkvl, g_qkvl);
    cudaGetSymbolAddress((void**)&xhi, g_xhi);
    cudaGetSymbolAddress((void**)&xlo, g_xlo);
    cudaGetSymbolAddress((void**)&ahi, g_ahi);
    cudaGetSymbolAddress((void**)&alo, g_alo);
    cudaGetSymbolAddress((void**)&wahi, g_wahi);
    cudaGetSymbolAddress((void**)&walo, g_walo);
    cudaGetSymbolAddress((void**)&wphi, g_wphi);
    cudaGetSymbolAddress((void**)&wplo, g_wplo);

    cudaFuncSetAttribute(mma_gemm_kernel,
                         cudaFuncAttributeMaxDynamicSharedMemorySize, MMA_SMEM_BYTES);
    cudaFuncSetAttribute(flash_attn_hmma,
                         cudaFuncAttributeMaxDynamicSharedMemorySize, ATT_SMEM);

    // 0) prep: split x, transpose+split weights
    {
        const int n4 = MROWS * EMBED / 4;
        split_bf16_kernel<<<(n4 + 255) / 256, 256>>>(x, xhi, xlo, n4);
        dim3 gwa(N3 / 32, EMBED / 32);
        transpose_split_kernel<<<gwa, 256>>>(W_atten, wahi, walo, EMBED, N3);
        dim3 gwp(EMBED / 32, EMBED / 32);
        transpose_split_kernel<<<gwp, 256>>>(W_proj, wphi, wplo, EMBED, EMBED);
    }
    // 1) qkv = x @ W_atten + b_atten -> split bf16 hi/lo directly
    {
        dim3 grid(N3 / GBN, MROWS / GBM);
        mma_gemm_kernel<<<grid, 256, MMA_SMEM_BYTES>>>(
            xhi, xlo, wahi, walo, b_atten, nullptr, qkvh, qkvl, MROWS, N3, EMBED);
    }
    // 2) causal flash attention (HMMA) -> att split bf16 hi/lo
    {
        dim3 grid(SEQ / BQ, BATCH * HEADS);
        flash_attn_hmma<<<grid, 256, ATT_SMEM>>>(qkvh, qkvl, ahi, alo);
    }
    // 3) out = att @ W_proj + b_proj  (fp32 out)
    {
        dim3 grid(EMBED / GBN, MROWS / GBM);
        mma_gemm_kernel<<<grid, 256, MMA_SMEM_BYTES>>>(
            ahi, alo, wphi, wplo, b_proj, out, nullptr, nullptr, MROWS, EMBED, EMBED);
    }
}